// round 11
// baseline (speedup 1.0000x reference)
#include <cuda_runtime.h>

namespace {

constexpr int Hh = 8, Ll = 2048, Dd = 512;
constexpr float PIf = 3.14159265358979323846f;
using u64 = unsigned long long;

// ---- packed f32x2 complex ops (re in lane0, im in lane1) -------------------
__device__ __forceinline__ u64 pk2(float x, float y) {
  u64 r; asm("mov.b64 %0, {%1, %2};" : "=l"(r) : "f"(x), "f"(y)); return r;
}
__device__ __forceinline__ void unpk(u64 v, float& x, float& y) {
  asm("mov.b64 {%0, %1}, %2;" : "=f"(x), "=f"(y) : "l"(v));
}
__device__ __forceinline__ u64 padd(u64 a, u64 b) {
  u64 r; asm("add.rn.f32x2 %0, %1, %2;" : "=l"(r) : "l"(a), "l"(b)); return r;
}
__device__ __forceinline__ u64 pmul(u64 a, u64 b) {
  u64 r; asm("mul.rn.f32x2 %0, %1, %2;" : "=l"(r) : "l"(a), "l"(b)); return r;
}
__device__ __forceinline__ u64 pfma(u64 a, u64 b, u64 c) {
  u64 r; asm("fma.rn.f32x2 %0, %1, %2, %3;" : "=l"(r) : "l"(a), "l"(b), "l"(c)); return r;
}
__device__ __forceinline__ u64 pswap(u64 v) { float x, y; unpk(v, x, y); return pk2(y, x); }
template<int S>
__device__ __forceinline__ u64 prot(u64 v) {   // * -i (S<0) or * +i (S>0)
  float x, y; unpk(v, x, y);
  return (S < 0) ? pk2(y, -x) : pk2(-y, x);
}
// scalar-twiddle complex multiply on a packed value
__device__ __forceinline__ u64 cmulsc(u64 v, float c, float s) {
  float x, y; unpk(v, x, y);
  return pk2(x * c - y * s, x * s + y * c);
}

// 8-point DFT on packed values, natural order. S=-1 forward, +1 inverse.
template<int S>
__device__ __forceinline__ void dft8p(u64 v[8]) {
  const float r = 0.70710678118654752440f;
  const u64 NEG1 = pk2(-1.f, -1.f);
  const u64 PM   = pk2( 1.f, -1.f);
  const u64 MP   = pk2(-1.f,  1.f);
  const u64 RR   = pk2(  r,    r);
  const u64 NR   = pk2( -r,   -r);
  auto psub = [&](u64 a, u64 b) { return pfma(b, NEG1, a); };

  u64 a0 = padd(v[0], v[4]), a1 = padd(v[1], v[5]);
  u64 a2 = padd(v[2], v[6]), a3 = padd(v[3], v[7]);
  u64 b0 = psub(v[0], v[4]), b1 = psub(v[1], v[5]);
  u64 b2 = psub(v[2], v[6]), b3 = psub(v[3], v[7]);

  b1 = pmul(pfma(pswap(b1), (S < 0) ? PM : MP, b1), RR);   // *W8^S
  b3 = pmul(pfma(pswap(b3), (S < 0) ? MP : PM, b3), NR);   // *W8^{3S}
  b2 = prot<S>(b2);

  {
    u64 e0 = padd(a0, a2), e1 = padd(a1, a3);
    u64 o0 = psub(a0, a2), t1 = psub(a1, a3);
    u64 o1 = prot<S>(t1);
    v[0] = padd(e0, e1); v[4] = psub(e0, e1);
    v[2] = padd(o0, o1); v[6] = psub(o0, o1);
  }
  {
    u64 e0 = padd(b0, b2), e1 = padd(b1, b3);
    u64 o0 = psub(b0, b2), t1 = psub(b1, b3);
    u64 o1 = prot<S>(t1);
    v[1] = padd(e0, e1); v[5] = psub(e0, e1);
    v[3] = padd(o0, o1); v[7] = psub(o0, o1);
  }
}

// Geometric twiddle stage: v[k] *= e^{i k th}, k=1..7.
// Odd harmonics from MUFU (__sincosf), evens by double-angle squaring.
__device__ __forceinline__ void twiddle8(u64 v[8], float th) {
  float c1, s1; __sincosf(th, &s1, &c1);
  v[1] = cmulsc(v[1], c1, s1);
  float c2 = c1 * c1 - s1 * s1, s2 = 2.f * c1 * s1;
  v[2] = cmulsc(v[2], c2, s2);
  float c3, s3; __sincosf(3.f * th, &s3, &c3);
  v[3] = cmulsc(v[3], c3, s3);
  float c4 = c2 * c2 - s2 * s2, s4 = 2.f * c2 * s2;
  v[4] = cmulsc(v[4], c4, s4);
  float c5, s5; __sincosf(5.f * th, &s5, &c5);
  v[5] = cmulsc(v[5], c5, s5);
  float c6 = c3 * c3 - s3 * s3, s6 = 2.f * c3 * s3;
  v[6] = cmulsc(v[6], c6, s6);
  float c7, s7; __sincosf(7.f * th, &s7, &c7);
  v[7] = cmulsc(v[7], c7, s7);
}

// In-warp 8x8 transpose within each group of 8 consecutive lanes.
// Before: lane (g, i) reg j holds M[i][j]. After: holds M[j][i].
// 3 butterfly stages (m = 1,2,4), 4 u64 shuffles each, in place.
__device__ __forceinline__ void transpose8(u64 v[8], int lane) {
#pragma unroll
  for (int m = 1; m < 8; m <<= 1) {
    const bool up = (lane & m) != 0;
#pragma unroll
    for (int p = 0; p < 8; ++p) {
      if (p & m) {
        const int lo = p ^ m;
        u64 send = up ? v[lo] : v[p];
        u64 got = __shfl_xor_sync(0xFFFFFFFFu, send, m, 32);
        if (up) v[lo] = got; else v[p] = got;
      }
    }
  }
}

// Half-warp phase-conflict-free swizzle for 8B values, logical 64a + 8b + c.
// phys [8:4] = (a2,a1,b2,b1,b0); [3:0] = (a0^b0, c2^b2, c1^b1, c0^b0).
// Invertible on each remaining access pattern's half-warp free-bit subspace
// (E1 writes {b0,c}, E1 reads {a0,c}, E4 writes {a0,c}... and gate {b,c0}) =>
// 2 wavefronts per 8B instruction (the floor).
__device__ __forceinline__ int swz(int a, int b, int c) {
  return ((a >> 1) << 7) | ((b >> 1) << 5) | ((b & 1) << 4)
       | (((a ^ b) & 1) << 3) | ((b ^ c) & 7);
}

// One block = HALF an (h,l) tile: 2 pair-rows, 128 threads.
// Radix-8 FFT512: E1 smem exchange, E2/E3 in-warp shuffle transposes
// (no crossbar traffic, no barrier), E4 smem exchange.
__global__ void __launch_bounds__(128, 10)
sgn_fft_kernel(const float* __restrict__ x, const float* __restrict__ wgt,
               float* __restrict__ out)
{
  __shared__ u64 sm[2][512];
  __shared__ float2 Vsm[512];

  const int tid  = threadIdx.x;
  const int s    = tid >> 6;              // pair-row within block (0..1)
  const int t    = tid & 63;
  const int bid  = blockIdx.x;
  const int hl   = bid >> 1;              // hl = h*2048 + l
  const int pb   = ((bid & 1) << 1) | s;  // batch pair 0..3

  const float2* __restrict__ wrow =
      reinterpret_cast<const float2*>(wgt) + (size_t)hl * Dd;

  // ---- gate staging with Hermitian pairing:
  // V_k = (W_k + conj(W_{-k})) / 1024 and V_{512-k} = conj(V_k).
#pragma unroll
  for (int i = tid; i < 256; i += 128) {
    const int m = (512 - i) & 511;
    float2 wk = __ldg(&wrow[i]);
    float2 wm = __ldg(&wrow[m]);
    float vx = (wk.x + wm.x) * (1.f / 1024.f);
    float vy = (wk.y - wm.y) * (1.f / 1024.f);
    Vsm[swz(i >> 6, (i >> 3) & 7, i & 7)] = make_float2(vx, vy);
    Vsm[swz(m >> 6, (m >> 3) & 7, m & 7)] = make_float2(vx, -vy);
  }
  if (tid == 0) {
    float2 w2 = __ldg(&wrow[256]);
    Vsm[swz(4, 0, 0)] = make_float2(2.f * w2.x * (1.f / 1024.f), 0.f);
  }

  // 32-bit element offsets (B*H*L*D = 2^26 < 2^31)
  const unsigned rowStride = (unsigned)(Hh * Ll) * (unsigned)Dd; // per-batch
  const unsigned base = (unsigned)hl * (unsigned)Dd;
  const unsigned off1 = (unsigned)pb * rowStride + base;
  const unsigned off2 = off1 + 4u * rowStride;
  const float* __restrict__ x1 = x + off1;
  const float* __restrict__ x2 = x + off2;

  u64 v[8];
  // z = x1 + i*x2, n = 64*n2 + t
#pragma unroll
  for (int n2 = 0; n2 < 8; ++n2)
    v[n2] = pk2(__ldg(&x1[(n2 << 6) + t]), __ldg(&x2[(n2 << 6) + t]));

  // ---- forward stage 1: DFT over n2 -> k0, twiddle e^{-2pi i t k0/512}
  dft8p<-1>(v);
  twiddle8(v, -2.f * PIf * (float)t * (1.f / 512.f));
  // ---- E1 (smem): redistribute so thread (k0, n0) gathers over n1
  {
    const int n1 = t >> 3, n0 = t & 7;
#pragma unroll
    for (int k = 0; k < 8; ++k) sm[s][swz(k, n1, n0)] = v[k];
  }
  // orders sm[s] AND the shared Vsm staging
  __syncthreads();

  // ---- forward stage 2: thread (k0, n0), DFT over n1 -> k1, tw e^{-2pi i n0 k1/64}
  const int k0 = t >> 3;
  const int n0 = t & 7;
#pragma unroll
  for (int j = 0; j < 8; ++j) v[j] = sm[s][swz(k0, j, n0)];
  dft8p<-1>(v);
  twiddle8(v, -2.f * PIf * (float)n0 * (1.f / 64.f));

  // ---- E2 (shuffle): transpose k1 <-> n0 within the 8-lane group of fixed k0.
  // After: thread (k0, k1) holds v over n0.
  transpose8(v, t);

  // ---- forward stage 3 (registers): thread (k0, k1), DFT over n0 -> k2
  const int k1 = t & 7;
  dft8p<-1>(v);
  // v[k2] = Z[k] at k = k0 + 8*k1 + 64*k2

  // ---- spectral gate (conflict-free smem)
#pragma unroll
  for (int k2 = 0; k2 < 8; ++k2) {
    float2 Vv = Vsm[swz(k2, k1, k0)];
    v[k2] = cmulsc(v[k2], Vv.x, Vv.y);
  }

  // ---- inverse stage 3': IDFT over k2 -> n0', twiddle e^{+2pi i n0' k1/64}
  dft8p<1>(v);
  twiddle8(v, 2.f * PIf * (float)k1 * (1.f / 64.f));

  // ---- E3 (shuffle): transpose n0' <-> k1 within the same 8-lane group.
  // After: thread (k0, n0) holds v over k1.
  transpose8(v, t);

  // ---- inverse stage 2': thread (k0, n0), IDFT over k1 -> n1,
  //      twiddle e^{+2pi i (8*n1+n0)*k0/512} via direct MUFU sincos
  dft8p<1>(v);
  {
    const float thb = 2.f * PIf * (1.f / 512.f) * (float)k0;
#pragma unroll
    for (int n1 = 0; n1 < 8; ++n1) {
      float sn, cs; __sincosf(thb * (float)((n1 << 3) + n0), &sn, &cs);
      v[n1] = cmulsc(v[n1], cs, sn);
    }
  }

  // ---- E4 (smem): protect buffer reuse (E1 reads by the partner warp may
  // still be in flight), then redistribute for the final stage.
  __syncthreads();
#pragma unroll
  for (int n1 = 0; n1 < 8; ++n1) sm[s][swz(k0, n1, n0)] = v[n1];
  __syncthreads();

  // ---- inverse stage 1': thread t=(n1,n0), IDFT over k0 -> n2, store
#pragma unroll
  for (int a = 0; a < 8; ++a) v[a] = sm[s][swz(a, t >> 3, t & 7)];
  dft8p<1>(v);

  float* __restrict__ o1 = out + off1;
  float* __restrict__ o2 = out + off2;
#pragma unroll
  for (int n2 = 0; n2 < 8; ++n2) {
    float re, im; unpk(v[n2], re, im);
    o1[(n2 << 6) + t] = re;   // Re -> batch pb
    o2[(n2 << 6) + t] = im;   // Im -> batch pb+4
  }
}

} // namespace

extern "C" void kernel_launch(void* const* d_in, const int* in_sizes, int n_in,
                              void* d_out, int out_size) {
  const float* x   = (const float*)d_in[0];
  // d_in[1] is the (unused) mask
  const float* wgt = (const float*)d_in[2];
  float* out       = (float*)d_out;
  sgn_fft_kernel<<<Hh * Ll * 2, 128>>>(x, wgt, out);
}

// round 12
// speedup vs baseline: 1.0638x; 1.0638x over previous
#include <cuda_runtime.h>

namespace {

constexpr int Hh = 8, Ll = 2048, Dd = 512;
constexpr float PIf = 3.14159265358979323846f;
using u64 = unsigned long long;

// ---- packed f32x2 complex ops (re in lane0, im in lane1) -------------------
__device__ __forceinline__ u64 pk2(float x, float y) {
  u64 r; asm("mov.b64 %0, {%1, %2};" : "=l"(r) : "f"(x), "f"(y)); return r;
}
__device__ __forceinline__ void unpk(u64 v, float& x, float& y) {
  asm("mov.b64 {%0, %1}, %2;" : "=f"(x), "=f"(y) : "l"(v));
}
__device__ __forceinline__ u64 padd(u64 a, u64 b) {
  u64 r; asm("add.rn.f32x2 %0, %1, %2;" : "=l"(r) : "l"(a), "l"(b)); return r;
}
__device__ __forceinline__ u64 pmul(u64 a, u64 b) {
  u64 r; asm("mul.rn.f32x2 %0, %1, %2;" : "=l"(r) : "l"(a), "l"(b)); return r;
}
__device__ __forceinline__ u64 pfma(u64 a, u64 b, u64 c) {
  u64 r; asm("fma.rn.f32x2 %0, %1, %2, %3;" : "=l"(r) : "l"(a), "l"(b), "l"(c)); return r;
}
__device__ __forceinline__ u64 pswap(u64 v) { float x, y; unpk(v, x, y); return pk2(y, x); }
template<int S>
__device__ __forceinline__ u64 prot(u64 v) {   // * -i (S<0) or * +i (S>0)
  float x, y; unpk(v, x, y);
  return (S < 0) ? pk2(y, -x) : pk2(-y, x);
}
// scalar-twiddle complex multiply on a packed value
__device__ __forceinline__ u64 cmulsc(u64 v, float c, float s) {
  float x, y; unpk(v, x, y);
  return pk2(x * c - y * s, x * s + y * c);
}

// 8-point DFT on packed values, natural order. S=-1 forward, +1 inverse.
template<int S>
__device__ __forceinline__ void dft8p(u64 v[8]) {
  const float r = 0.70710678118654752440f;
  const u64 NEG1 = pk2(-1.f, -1.f);
  const u64 PM   = pk2( 1.f, -1.f);
  const u64 MP   = pk2(-1.f,  1.f);
  const u64 RR   = pk2(  r,    r);
  const u64 NR   = pk2( -r,   -r);
  auto psub = [&](u64 a, u64 b) { return pfma(b, NEG1, a); };

  u64 a0 = padd(v[0], v[4]), a1 = padd(v[1], v[5]);
  u64 a2 = padd(v[2], v[6]), a3 = padd(v[3], v[7]);
  u64 b0 = psub(v[0], v[4]), b1 = psub(v[1], v[5]);
  u64 b2 = psub(v[2], v[6]), b3 = psub(v[3], v[7]);

  b1 = pmul(pfma(pswap(b1), (S < 0) ? PM : MP, b1), RR);   // *W8^S
  b3 = pmul(pfma(pswap(b3), (S < 0) ? MP : PM, b3), NR);   // *W8^{3S}
  b2 = prot<S>(b2);

  {
    u64 e0 = padd(a0, a2), e1 = padd(a1, a3);
    u64 o0 = psub(a0, a2), t1 = psub(a1, a3);
    u64 o1 = prot<S>(t1);
    v[0] = padd(e0, e1); v[4] = psub(e0, e1);
    v[2] = padd(o0, o1); v[6] = psub(o0, o1);
  }
  {
    u64 e0 = padd(b0, b2), e1 = padd(b1, b3);
    u64 o0 = psub(b0, b2), t1 = psub(b1, b3);
    u64 o1 = prot<S>(t1);
    v[1] = padd(e0, e1); v[5] = psub(e0, e1);
    v[3] = padd(o0, o1); v[7] = psub(o0, o1);
  }
}

// Geometric twiddle stage: v[k] *= e^{i k th}, k=1..7.
// Odd harmonics from MUFU (__sincosf), evens by double-angle squaring.
__device__ __forceinline__ void twiddle8(u64 v[8], float th) {
  float c1, s1; __sincosf(th, &s1, &c1);
  v[1] = cmulsc(v[1], c1, s1);
  float c2 = c1 * c1 - s1 * s1, s2 = 2.f * c1 * s1;
  v[2] = cmulsc(v[2], c2, s2);
  float c3, s3; __sincosf(3.f * th, &s3, &c3);
  v[3] = cmulsc(v[3], c3, s3);
  float c4 = c2 * c2 - s2 * s2, s4 = 2.f * c2 * s2;
  v[4] = cmulsc(v[4], c4, s4);
  float c5, s5; __sincosf(5.f * th, &s5, &c5);
  v[5] = cmulsc(v[5], c5, s5);
  float c6 = c3 * c3 - s3 * s3, s6 = 2.f * c3 * s3;
  v[6] = cmulsc(v[6], c6, s6);
  float c7, s7; __sincosf(7.f * th, &s7, &c7);
  v[7] = cmulsc(v[7], c7, s7);
}

// Half-warp phase-conflict-free swizzle for 8B values, logical 64a + 8b + c.
// phys [8:4] = (a2,a1,b2,b1,b0); [3:0] = (a0^b0, c2^b2, c1^b1, c0^b0).
// Invertible on each access pattern's half-warp free-bit subspace =>
// 2 wavefronts per 8B instruction (the floor) on every exchange and the gate.
__device__ __forceinline__ int swz(int a, int b, int c) {
  return ((a >> 1) << 7) | ((b >> 1) << 5) | ((b & 1) << 4)
       | (((a ^ b) & 1) << 3) | ((b ^ c) & 7);
}

// One block = HALF an (h,l) tile: 2 pair-rows, 128 threads, 12 blocks/SM.
// Small independent blocks decorrelate barrier waits; 48 resident warps
// fill the L1-crossbar idle cycles. Each exchange phase reads and writes
// the SAME per-thread address set, so WAR hazards are thread-local and a
// single barrier per phase suffices.
__global__ void __launch_bounds__(128, 12)
sgn_fft_kernel(const float* __restrict__ x, const float* __restrict__ wgt,
               float* __restrict__ out)
{
  __shared__ u64 sm[2][512];
  __shared__ float2 Vsm[512];

  const int tid  = threadIdx.x;
  const int s    = tid >> 6;              // pair-row within block (0..1)
  const int t    = tid & 63;
  const int bid  = blockIdx.x;
  const int hl   = bid >> 1;              // hl = h*2048 + l
  const int pb   = ((bid & 1) << 1) | s;  // batch pair 0..3

  const float2* __restrict__ wrow =
      reinterpret_cast<const float2*>(wgt) + (size_t)hl * Dd;

  // ---- gate staging with Hermitian pairing:
  // V_k = (W_k + conj(W_{-k})) / 1024 and V_{512-k} = conj(V_k).
#pragma unroll
  for (int i = tid; i < 256; i += 128) {
    const int m = (512 - i) & 511;
    float2 wk = __ldg(&wrow[i]);
    float2 wm = __ldg(&wrow[m]);
    float vx = (wk.x + wm.x) * (1.f / 1024.f);
    float vy = (wk.y - wm.y) * (1.f / 1024.f);
    Vsm[swz(i >> 6, (i >> 3) & 7, i & 7)] = make_float2(vx, vy);
    Vsm[swz(m >> 6, (m >> 3) & 7, m & 7)] = make_float2(vx, -vy);
  }
  if (tid == 0) {
    float2 w2 = __ldg(&wrow[256]);
    Vsm[swz(4, 0, 0)] = make_float2(2.f * w2.x * (1.f / 1024.f), 0.f);
  }

  // 32-bit element offsets (B*H*L*D = 2^26 < 2^31)
  const unsigned rowStride = (unsigned)(Hh * Ll) * (unsigned)Dd; // per-batch
  const unsigned base = (unsigned)hl * (unsigned)Dd;
  const unsigned off1 = (unsigned)pb * rowStride + base;
  const unsigned off2 = off1 + 4u * rowStride;
  const float* __restrict__ x1 = x + off1;
  const float* __restrict__ x2 = x + off2;

  u64 v[8];
  // z = x1 + i*x2, n = 64*n2 + t
#pragma unroll
  for (int n2 = 0; n2 < 8; ++n2)
    v[n2] = pk2(__ldg(&x1[(n2 << 6) + t]), __ldg(&x2[(n2 << 6) + t]));

  // ---- forward stage 1: DFT over n2 -> k0, twiddle e^{-2pi i t k0/512}
  dft8p<-1>(v);
  twiddle8(v, -2.f * PIf * (float)t * (1.f / 512.f));
  {
    const int n1 = t >> 3, n0 = t & 7;
#pragma unroll
    for (int k = 0; k < 8; ++k) sm[s][swz(k, n1, n0)] = v[k];
  }
  // orders sm[s] AND the shared Vsm staging
  __syncthreads();

  // ---- forward stage 2: thread (k0, n0), DFT over n1 -> k1, tw e^{-2pi i n0 k1/64}
  const int k0 = t >> 3;
  const int n0 = t & 7;
#pragma unroll
  for (int j = 0; j < 8; ++j) v[j] = sm[s][swz(k0, j, n0)];
  dft8p<-1>(v);
  twiddle8(v, -2.f * PIf * (float)n0 * (1.f / 64.f));
#pragma unroll
  for (int k = 0; k < 8; ++k) sm[s][swz(k0, k, n0)] = v[k];
  __syncthreads();

  // ---- forward stage 3 (registers): thread (k0, k1), DFT over n0 -> k2
  const int k1 = t & 7;
#pragma unroll
  for (int c = 0; c < 8; ++c) v[c] = sm[s][swz(k0, k1, c)];
  dft8p<-1>(v);
  // v[k2] = Z[k] at k = k0 + 8*k1 + 64*k2

  // ---- spectral gate (conflict-free smem)
#pragma unroll
  for (int k2 = 0; k2 < 8; ++k2) {
    float2 Vv = Vsm[swz(k2, k1, k0)];
    v[k2] = cmulsc(v[k2], Vv.x, Vv.y);
  }

  // ---- inverse stage 3': IDFT over k2 -> n0', twiddle e^{+2pi i n0' k1/64}
  dft8p<1>(v);
  twiddle8(v, 2.f * PIf * (float)k1 * (1.f / 64.f));
#pragma unroll
  for (int c = 0; c < 8; ++c) sm[s][swz(k0, k1, c)] = v[c];
  __syncthreads();

  // ---- inverse stage 2': thread (k0, n0), IDFT over k1 -> n1,
  //      twiddle e^{+2pi i (8*n1+n0)*k0/512} via direct MUFU sincos
#pragma unroll
  for (int j = 0; j < 8; ++j) v[j] = sm[s][swz(k0, j, n0)];
  dft8p<1>(v);
  {
    const float thb = 2.f * PIf * (1.f / 512.f) * (float)k0;
#pragma unroll
    for (int n1 = 0; n1 < 8; ++n1) {
      float sn, cs; __sincosf(thb * (float)((n1 << 3) + n0), &sn, &cs);
      v[n1] = cmulsc(v[n1], cs, sn);
    }
  }
#pragma unroll
  for (int n1 = 0; n1 < 8; ++n1) sm[s][swz(k0, n1, n0)] = v[n1];
  __syncthreads();

  // ---- inverse stage 1': thread t=(n1,n0), IDFT over k0 -> n2, store
#pragma unroll
  for (int a = 0; a < 8; ++a) v[a] = sm[s][swz(a, t >> 3, t & 7)];
  dft8p<1>(v);

  float* __restrict__ o1 = out + off1;
  float* __restrict__ o2 = out + off2;
#pragma unroll
  for (int n2 = 0; n2 < 8; ++n2) {
    float re, im; unpk(v[n2], re, im);
    o1[(n2 << 6) + t] = re;   // Re -> batch pb
    o2[(n2 << 6) + t] = im;   // Im -> batch pb+4
  }
}

} // namespace

extern "C" void kernel_launch(void* const* d_in, const int* in_sizes, int n_in,
                              void* d_out, int out_size) {
  const float* x   = (const float*)d_in[0];
  // d_in[1] is the (unused) mask
  const float* wgt = (const float*)d_in[2];
  float* out       = (float*)d_out;
  sgn_fft_kernel<<<Hh * Ll * 2, 128>>>(x, wgt, out);
}

// round 13
// speedup vs baseline: 1.1642x; 1.0943x over previous
#include <cuda_runtime.h>

namespace {

constexpr int Hh = 8, Ll = 2048, Dd = 512;
constexpr float PIf = 3.14159265358979323846f;
using u64 = unsigned long long;

// ---- packed f32x2 complex ops (re in lane0, im in lane1) -------------------
__device__ __forceinline__ u64 pk2(float x, float y) {
  u64 r; asm("mov.b64 %0, {%1, %2};" : "=l"(r) : "f"(x), "f"(y)); return r;
}
__device__ __forceinline__ void unpk(u64 v, float& x, float& y) {
  asm("mov.b64 {%0, %1}, %2;" : "=f"(x), "=f"(y) : "l"(v));
}
__device__ __forceinline__ u64 padd(u64 a, u64 b) {
  u64 r; asm("add.rn.f32x2 %0, %1, %2;" : "=l"(r) : "l"(a), "l"(b)); return r;
}
__device__ __forceinline__ u64 pmul(u64 a, u64 b) {
  u64 r; asm("mul.rn.f32x2 %0, %1, %2;" : "=l"(r) : "l"(a), "l"(b)); return r;
}
__device__ __forceinline__ u64 pfma(u64 a, u64 b, u64 c) {
  u64 r; asm("fma.rn.f32x2 %0, %1, %2, %3;" : "=l"(r) : "l"(a), "l"(b), "l"(c)); return r;
}
__device__ __forceinline__ u64 pswap(u64 v) { float x, y; unpk(v, x, y); return pk2(y, x); }
template<int S>
__device__ __forceinline__ u64 prot(u64 v) {   // * -i (S<0) or * +i (S>0)
  float x, y; unpk(v, x, y);
  return (S < 0) ? pk2(y, -x) : pk2(-y, x);
}
// scalar-twiddle complex multiply on a packed value
__device__ __forceinline__ u64 cmulsc(u64 v, float c, float s) {
  float x, y; unpk(v, x, y);
  return pk2(x * c - y * s, x * s + y * c);
}

// 8-point DFT on packed values, natural order. S=-1 forward, +1 inverse.
template<int S>
__device__ __forceinline__ void dft8p(u64 v[8]) {
  const float r = 0.70710678118654752440f;
  const u64 NEG1 = pk2(-1.f, -1.f);
  const u64 PM   = pk2( 1.f, -1.f);
  const u64 MP   = pk2(-1.f,  1.f);
  const u64 RR   = pk2(  r,    r);
  const u64 NR   = pk2( -r,   -r);
  auto psub = [&](u64 a, u64 b) { return pfma(b, NEG1, a); };

  u64 a0 = padd(v[0], v[4]), a1 = padd(v[1], v[5]);
  u64 a2 = padd(v[2], v[6]), a3 = padd(v[3], v[7]);
  u64 b0 = psub(v[0], v[4]), b1 = psub(v[1], v[5]);
  u64 b2 = psub(v[2], v[6]), b3 = psub(v[3], v[7]);

  b1 = pmul(pfma(pswap(b1), (S < 0) ? PM : MP, b1), RR);   // *W8^S
  b3 = pmul(pfma(pswap(b3), (S < 0) ? MP : PM, b3), NR);   // *W8^{3S}
  b2 = prot<S>(b2);

  {
    u64 e0 = padd(a0, a2), e1 = padd(a1, a3);
    u64 o0 = psub(a0, a2), t1 = psub(a1, a3);
    u64 o1 = prot<S>(t1);
    v[0] = padd(e0, e1); v[4] = psub(e0, e1);
    v[2] = padd(o0, o1); v[6] = psub(o0, o1);
  }
  {
    u64 e0 = padd(b0, b2), e1 = padd(b1, b3);
    u64 o0 = psub(b0, b2), t1 = psub(b1, b3);
    u64 o1 = prot<S>(t1);
    v[1] = padd(e0, e1); v[5] = psub(e0, e1);
    v[3] = padd(o0, o1); v[7] = psub(o0, o1);
  }
}

// Geometric twiddle stage: v[k] *= e^{i k th}, k=1..7.
// Odd harmonics from MUFU (__sincosf), evens by double-angle squaring.
__device__ __forceinline__ void twiddle8(u64 v[8], float th) {
  float c1, s1; __sincosf(th, &s1, &c1);
  v[1] = cmulsc(v[1], c1, s1);
  float c2 = c1 * c1 - s1 * s1, s2 = 2.f * c1 * s1;
  v[2] = cmulsc(v[2], c2, s2);
  float c3, s3; __sincosf(3.f * th, &s3, &c3);
  v[3] = cmulsc(v[3], c3, s3);
  float c4 = c2 * c2 - s2 * s2, s4 = 2.f * c2 * s2;
  v[4] = cmulsc(v[4], c4, s4);
  float c5, s5; __sincosf(5.f * th, &s5, &c5);
  v[5] = cmulsc(v[5], c5, s5);
  float c6 = c3 * c3 - s3 * s3, s6 = 2.f * c3 * s3;
  v[6] = cmulsc(v[6], c6, s6);
  float c7, s7; __sincosf(7.f * th, &s7, &c7);
  v[7] = cmulsc(v[7], c7, s7);
}

// Half-warp phase-conflict-free swizzle for 8B values, logical 64a + 8b + c.
// phys [8:4] = (a2,a1,b2,b1,b0); [3:0] = (a0^b0, c2^b2, c1^b1, c0^b0).
// Invertible on each access pattern's 16-lane-phase free-bit subspace =>
// 2 wavefronts per 8B instruction (the floor) on every exchange and the gate.
__device__ __forceinline__ int swz(int a, int b, int c) {
  return ((a >> 1) << 7) | ((b >> 1) << 5) | ((b & 1) << 4)
       | (((a ^ b) & 1) << 3) | ((b ^ c) & 7);
}

// One block = one (h,l) tile; one WARP per pair-row FFT (batches w and w+4
// packed as z = x1 + i*x2). Each of the 32 lanes carries TWO of the old
// 64-lane columns (t = l and t = l+32), so all exchanges are warp-internal:
// STS -> __syncwarp -> LDS. No block barriers in the FFT (the only
// __syncthreads orders the shared gate staging). Every exchange's write set
// equals the same thread-half's previous read set, so WAR is thread-local.
__global__ void __launch_bounds__(128, 8)
sgn_fft_kernel(const float* __restrict__ x, const float* __restrict__ wgt,
               float* __restrict__ out)
{
  __shared__ u64 sm[4][512];
  __shared__ float2 Vsm[512];

  const int tid = threadIdx.x;
  const int w   = tid >> 5;              // pair-row == batch pair 0..3
  const int l   = tid & 31;
  const int hl  = blockIdx.x;            // hl = h*2048 + l_seq

  const float2* __restrict__ wrow =
      reinterpret_cast<const float2*>(wgt) + (size_t)hl * Dd;

  // ---- gate staging with Hermitian pairing (once per block):
  // V_k = (W_k + conj(W_{-k})) / 1024 and V_{512-k} = conj(V_k).
#pragma unroll
  for (int i = tid; i < 256; i += 128) {
    const int m = (512 - i) & 511;
    float2 wk = __ldg(&wrow[i]);
    float2 wm = __ldg(&wrow[m]);
    float vx = (wk.x + wm.x) * (1.f / 1024.f);
    float vy = (wk.y - wm.y) * (1.f / 1024.f);
    Vsm[swz(i >> 6, (i >> 3) & 7, i & 7)] = make_float2(vx, vy);
    Vsm[swz(m >> 6, (m >> 3) & 7, m & 7)] = make_float2(vx, -vy);
  }
  if (tid == 0) {
    float2 w2 = __ldg(&wrow[256]);
    Vsm[swz(4, 0, 0)] = make_float2(2.f * w2.x * (1.f / 1024.f), 0.f);
  }
  __syncthreads();   // the ONLY block barrier

  // 32-bit element offsets (B*H*L*D = 2^26 < 2^31)
  const unsigned rowStride = (unsigned)(Hh * Ll) * (unsigned)Dd; // per-batch
  const unsigned off1 = (unsigned)w * rowStride + (unsigned)hl * (unsigned)Dd;
  const unsigned off2 = off1 + 4u * rowStride;
  const float* __restrict__ x1 = x + off1;
  const float* __restrict__ x2 = x + off2;

  u64 v[2][8];

  // ---- phase A: load + forward stage 1 + E1 write
#pragma unroll
  for (int q = 0; q < 2; ++q) {
    const int t = l + (q << 5);
#pragma unroll
    for (int n2 = 0; n2 < 8; ++n2)
      v[q][n2] = pk2(__ldg(&x1[(n2 << 6) + t]), __ldg(&x2[(n2 << 6) + t]));
    dft8p<-1>(v[q]);
    twiddle8(v[q], -2.f * PIf * (float)t * (1.f / 512.f));
    const int n1 = t >> 3, n0 = t & 7;
#pragma unroll
    for (int k = 0; k < 8; ++k) sm[w][swz(k, n1, n0)] = v[q][k];
  }
  __syncwarp();

  // ---- phase B: E1 read + forward stage 2 + E2 write
#pragma unroll
  for (int q = 0; q < 2; ++q) {
    const int t = l + (q << 5);
    const int k0 = t >> 3, n0 = t & 7;
#pragma unroll
    for (int j = 0; j < 8; ++j) v[q][j] = sm[w][swz(k0, j, n0)];
    dft8p<-1>(v[q]);
    twiddle8(v[q], -2.f * PIf * (float)n0 * (1.f / 64.f));
#pragma unroll
    for (int k = 0; k < 8; ++k) sm[w][swz(k0, k, n0)] = v[q][k];
  }
  __syncwarp();

  // ---- phase C: E2 read + stage 3 + gate + inverse stage 3' + E3 write
#pragma unroll
  for (int q = 0; q < 2; ++q) {
    const int t = l + (q << 5);
    const int k0 = t >> 3, k1 = t & 7;
#pragma unroll
    for (int c = 0; c < 8; ++c) v[q][c] = sm[w][swz(k0, k1, c)];
    dft8p<-1>(v[q]);
    // v[q][k2] = Z[k] at k = k0 + 8*k1 + 64*k2
#pragma unroll
    for (int k2 = 0; k2 < 8; ++k2) {
      float2 Vv = Vsm[swz(k2, k1, k0)];
      v[q][k2] = cmulsc(v[q][k2], Vv.x, Vv.y);
    }
    dft8p<1>(v[q]);
    twiddle8(v[q], 2.f * PIf * (float)k1 * (1.f / 64.f));
#pragma unroll
    for (int c = 0; c < 8; ++c) sm[w][swz(k0, k1, c)] = v[q][c];
  }
  __syncwarp();

  // ---- phase D: E3 read + inverse stage 2' + E4 write
#pragma unroll
  for (int q = 0; q < 2; ++q) {
    const int t = l + (q << 5);
    const int k0 = t >> 3, n0 = t & 7;
#pragma unroll
    for (int j = 0; j < 8; ++j) v[q][j] = sm[w][swz(k0, j, n0)];
    dft8p<1>(v[q]);
    {
      const float thb = 2.f * PIf * (1.f / 512.f) * (float)k0;
#pragma unroll
      for (int n1 = 0; n1 < 8; ++n1) {
        float sn, cs; __sincosf(thb * (float)((n1 << 3) + n0), &sn, &cs);
        v[q][n1] = cmulsc(v[q][n1], cs, sn);
      }
    }
#pragma unroll
    for (int n1 = 0; n1 < 8; ++n1) sm[w][swz(k0, n1, n0)] = v[q][n1];
  }
  __syncwarp();

  // ---- phase E: E4 read + inverse stage 1' + store
  float* __restrict__ o1 = out + off1;
  float* __restrict__ o2 = out + off2;
#pragma unroll
  for (int q = 0; q < 2; ++q) {
    const int t = l + (q << 5);
    const int n1 = t >> 3, n0 = t & 7;
#pragma unroll
    for (int a = 0; a < 8; ++a) v[q][a] = sm[w][swz(a, n1, n0)];
    dft8p<1>(v[q]);
#pragma unroll
    for (int n2 = 0; n2 < 8; ++n2) {
      float re, im; unpk(v[q][n2], re, im);
      o1[(n2 << 6) + t] = re;   // Re -> batch w
      o2[(n2 << 6) + t] = im;   // Im -> batch w+4
    }
  }
}

} // namespace

extern "C" void kernel_launch(void* const* d_in, const int* in_sizes, int n_in,
                              void* d_out, int out_size) {
  const float* x   = (const float*)d_in[0];
  // d_in[1] is the (unused) mask
  const float* wgt = (const float*)d_in[2];
  float* out       = (float*)d_out;
  sgn_fft_kernel<<<Hh * Ll, 128>>>(x, wgt, out);
}

// round 15
// speedup vs baseline: 1.2286x; 1.0554x over previous
#include <cuda_runtime.h>

namespace {

constexpr int Hh = 8, Ll = 2048, Dd = 512;
constexpr float PIf = 3.14159265358979323846f;
using u64 = unsigned long long;

// ---- packed f32x2 complex ops (re in lane0, im in lane1) -------------------
__device__ __forceinline__ u64 pk2(float x, float y) {
  u64 r; asm("mov.b64 %0, {%1, %2};" : "=l"(r) : "f"(x), "f"(y)); return r;
}
__device__ __forceinline__ void unpk(u64 v, float& x, float& y) {
  asm("mov.b64 {%0, %1}, %2;" : "=f"(x), "=f"(y) : "l"(v));
}
__device__ __forceinline__ u64 padd(u64 a, u64 b) {
  u64 r; asm("add.rn.f32x2 %0, %1, %2;" : "=l"(r) : "l"(a), "l"(b)); return r;
}
__device__ __forceinline__ u64 pmul(u64 a, u64 b) {
  u64 r; asm("mul.rn.f32x2 %0, %1, %2;" : "=l"(r) : "l"(a), "l"(b)); return r;
}
__device__ __forceinline__ u64 pfma(u64 a, u64 b, u64 c) {
  u64 r; asm("fma.rn.f32x2 %0, %1, %2, %3;" : "=l"(r) : "l"(a), "l"(b), "l"(c)); return r;
}
__device__ __forceinline__ u64 pswap(u64 v) { float x, y; unpk(v, x, y); return pk2(y, x); }
template<int S>
__device__ __forceinline__ u64 prot(u64 v) {   // * -i (S<0) or * +i (S>0)
  float x, y; unpk(v, x, y);
  return (S < 0) ? pk2(y, -x) : pk2(-y, x);
}
__device__ __forceinline__ u64 cmulsc(u64 v, float c, float s) {
  float x, y; unpk(v, x, y);
  return pk2(x * c - y * s, x * s + y * c);
}

// 8-point DFT on packed values, natural order. S=-1 forward, +1 inverse.
template<int S>
__device__ __forceinline__ void dft8p(u64 v[8]) {
  const float r = 0.70710678118654752440f;
  const u64 NEG1 = pk2(-1.f, -1.f);
  const u64 PM   = pk2( 1.f, -1.f);
  const u64 MP   = pk2(-1.f,  1.f);
  const u64 RR   = pk2(  r,    r);
  const u64 NR   = pk2( -r,   -r);
  auto psub = [&](u64 a, u64 b) { return pfma(b, NEG1, a); };

  u64 a0 = padd(v[0], v[4]), a1 = padd(v[1], v[5]);
  u64 a2 = padd(v[2], v[6]), a3 = padd(v[3], v[7]);
  u64 b0 = psub(v[0], v[4]), b1 = psub(v[1], v[5]);
  u64 b2 = psub(v[2], v[6]), b3 = psub(v[3], v[7]);

  b1 = pmul(pfma(pswap(b1), (S < 0) ? PM : MP, b1), RR);   // *W8^S
  b3 = pmul(pfma(pswap(b3), (S < 0) ? MP : PM, b3), NR);   // *W8^{3S}
  b2 = prot<S>(b2);

  {
    u64 e0 = padd(a0, a2), e1 = padd(a1, a3);
    u64 o0 = psub(a0, a2), t1 = psub(a1, a3);
    u64 o1 = prot<S>(t1);
    v[0] = padd(e0, e1); v[4] = psub(e0, e1);
    v[2] = padd(o0, o1); v[6] = psub(o0, o1);
  }
  {
    u64 e0 = padd(b0, b2), e1 = padd(b1, b3);
    u64 o0 = psub(b0, b2), t1 = psub(b1, b3);
    u64 o1 = prot<S>(t1);
    v[1] = padd(e0, e1); v[5] = psub(e0, e1);
    v[3] = padd(o0, o1); v[7] = psub(o0, o1);
  }
}

// 16-point DFT, natural in/out: X[k] = sum_m v[m] e^{S 2pi i mk/16}.
// Radix-2 DIF split + two dft8p; odd-branch twiddles are constants.
template<int S>
__device__ __forceinline__ void dft16p(u64 v[16]) {
  const u64 NEG1 = pk2(-1.f, -1.f);
  u64 e[8], o[8];
#pragma unroll
  for (int r = 0; r < 8; ++r) {
    e[r] = padd(v[r], v[r + 8]);
    o[r] = pfma(v[r + 8], NEG1, v[r]);
  }
  o[1] = cmulsc(o[1],  0.923879533f, S * 0.382683432f);
  o[2] = cmulsc(o[2],  0.707106781f, S * 0.707106781f);
  o[3] = cmulsc(o[3],  0.382683432f, S * 0.923879533f);
  o[4] = prot<S>(o[4]);
  o[5] = cmulsc(o[5], -0.382683432f, S * 0.923879533f);
  o[6] = cmulsc(o[6], -0.707106781f, S * 0.707106781f);
  o[7] = cmulsc(o[7], -0.923879533f, S * 0.382683432f);
  dft8p<S>(e);
  dft8p<S>(o);
#pragma unroll
  for (int k = 0; k < 8; ++k) { v[2 * k] = e[k]; v[2 * k + 1] = o[k]; }
}

// Geometric twiddle: v[k] *= e^{i k th}, k = 1..15.
// Odd harmonics via MUFU sincos, evens by double-angle squaring.
__device__ __forceinline__ void twiddle16(u64 v[16], float th) {
  float c1, s1; __sincosf(th, &s1, &c1);        v[1]  = cmulsc(v[1],  c1, s1);
  float c2 = c1*c1 - s1*s1, s2 = 2.f*c1*s1;     v[2]  = cmulsc(v[2],  c2, s2);
  float c3, s3; __sincosf(3.f*th, &s3, &c3);    v[3]  = cmulsc(v[3],  c3, s3);
  float c4 = c2*c2 - s2*s2, s4 = 2.f*c2*s2;     v[4]  = cmulsc(v[4],  c4, s4);
  float c5, s5; __sincosf(5.f*th, &s5, &c5);    v[5]  = cmulsc(v[5],  c5, s5);
  float c6 = c3*c3 - s3*s3, s6 = 2.f*c3*s3;     v[6]  = cmulsc(v[6],  c6, s6);
  float c7, s7; __sincosf(7.f*th, &s7, &c7);    v[7]  = cmulsc(v[7],  c7, s7);
  float c8 = c4*c4 - s4*s4, s8 = 2.f*c4*s4;     v[8]  = cmulsc(v[8],  c8, s8);
  float c9, s9; __sincosf(9.f*th, &s9, &c9);    v[9]  = cmulsc(v[9],  c9, s9);
  float cA = c5*c5 - s5*s5, sA = 2.f*c5*s5;     v[10] = cmulsc(v[10], cA, sA);
  float cB, sB; __sincosf(11.f*th, &sB, &cB);   v[11] = cmulsc(v[11], cB, sB);
  float cC = c6*c6 - s6*s6, sC = 2.f*c6*s6;     v[12] = cmulsc(v[12], cC, sC);
  float cD, sD; __sincosf(13.f*th, &sD, &cD);   v[13] = cmulsc(v[13], cD, sD);
  float cE = c7*c7 - s7*s7, sE = 2.f*c7*s7;     v[14] = cmulsc(v[14], cE, sE);
  float cF, sF; __sincosf(15.f*th, &sF, &cF);   v[15] = cmulsc(v[15], cF, sF);
}

// One block = one (h,l) tile; one WARP per pair-row FFT (batches w, w+4
// packed z = x1 + i*x2). Decomposition 512 = 16(reg) x 32(lanes), the
// lane FFT-32 = radix-2 shuffle butterfly x FFT-16(reg). Only TWO smem
// exchanges per FFT; gate layout is linear (fully coalesced).
// Exchange swizzle phi(l,k16) = (l<<4) | (k16 ^ (l&15)): conflict-free
// (2-wavefront floor) for all four access patterns.
__global__ void __launch_bounds__(128, 6)
sgn_fft_kernel(const float* __restrict__ x, const float* __restrict__ wgt,
               float* __restrict__ out)
{
  __shared__ u64 sm[4][512];
  __shared__ float2 Vsm[512];   // V[k] linear

  const int tid  = threadIdx.x;
  const int w    = tid >> 5;             // pair-row == batch pair 0..3
  const int lane = tid & 31;
  const int hl   = blockIdx.x;           // hl = h*2048 + l_seq

  const float2* __restrict__ wrow =
      reinterpret_cast<const float2*>(wgt) + (size_t)hl * Dd;

  // ---- gate staging (Hermitian pairing), linear layout:
  // V_k = (W_k + conj(W_{-k})) / 1024, V_{512-k} = conj(V_k).
#pragma unroll
  for (int i = tid; i < 256; i += 128) {
    const int m = (512 - i) & 511;
    float2 wk = __ldg(&wrow[i]);
    float2 wm = __ldg(&wrow[m]);
    float vx = (wk.x + wm.x) * (1.f / 1024.f);
    float vy = (wk.y - wm.y) * (1.f / 1024.f);
    Vsm[i] = make_float2(vx, vy);
    Vsm[m] = make_float2(vx, -vy);
  }
  if (tid == 0) {
    float2 w2 = __ldg(&wrow[256]);
    Vsm[256] = make_float2(2.f * w2.x * (1.f / 1024.f), 0.f);
  }
  __syncthreads();   // the ONLY block barrier

  const unsigned rowStride = (unsigned)(Hh * Ll) * (unsigned)Dd;
  const unsigned off1 = (unsigned)w * rowStride + (unsigned)hl * (unsigned)Dd;
  const unsigned off2 = off1 + 4u * rowStride;
  const float* __restrict__ x1 = x + off1;
  const float* __restrict__ x2 = x + off2;

  // butterfly constants
  const bool hi = (lane & 16) != 0;
  const float sg = hi ? -1.f : 1.f;
  const u64 SGN = pk2(sg, sg);
  const float W32c[16] = { 1.f, 0.980785280f, 0.923879533f, 0.831469612f,
    0.707106781f, 0.555570233f, 0.382683432f, 0.195090322f, 0.f,
    -0.195090322f, -0.382683432f, -0.555570233f, -0.707106781f,
    -0.831469612f, -0.923879533f, -0.980785280f };
  const float W32s[16] = { 0.f, 0.195090322f, 0.382683432f, 0.555570233f,
    0.707106781f, 0.831469612f, 0.923879533f, 0.980785280f, 1.f,
    0.980785280f, 0.923879533f, 0.831469612f, 0.707106781f, 0.555570233f,
    0.382683432f, 0.195090322f };

  u64 v[16];

  // ---- load: n = lane + 32 m (coalesced per m); z = x1 + i*x2
#pragma unroll
  for (int m = 0; m < 16; ++m)
    v[m] = pk2(__ldg(&x1[(m << 5) + lane]), __ldg(&x2[(m << 5) + lane]));

  // ---- forward inner: DFT16 over m -> k16, twiddle e^{-2pi i lane k16/512}
  dft16p<-1>(v);
  twiddle16(v, -2.f * PIf * (float)lane * (1.f / 512.f));

  // ---- E1 (smem): (lane holds all k16) -> (thread u holds k16=u%16, its l half)
  {
    const int lb = lane & 15;
#pragma unroll
    for (int k16 = 0; k16 < 16; ++k16)
      sm[w][(lane << 4) | (k16 ^ lb)] = v[k16];
  }
  __syncwarp();
  {
    const int k16u = lane & 15, off = lane & 16;
#pragma unroll
    for (int r = 0; r < 16; ++r)
      v[r] = sm[w][((r + off) << 4) | (k16u ^ r)];
  }

  // ---- forward outer FFT-32 over l: radix-2 cross-pair + DFT16(reg)
#pragma unroll
  for (int r = 0; r < 16; ++r) {
    u64 g = __shfl_xor_sync(0xFFFFFFFFu, v[r], 16);
    v[r] = pfma(v[r], SGN, g);          // low: a=v+g ; high: b0=g-v
  }
  if (hi) {
#pragma unroll
    for (int r = 1; r < 16; ++r) v[r] = cmulsc(v[r], W32c[r], -W32s[r]);
  }
  dft16p<-1>(v);
  // thread u reg j holds Z[k], k = (u&15) + (u&16) + 32 j

  // ---- spectral gate (linear, coalesced)
#pragma unroll
  for (int j = 0; j < 16; ++j) {
    float2 Vv = Vsm[(j << 5) + lane];
    v[j] = cmulsc(v[j], Vv.x, Vv.y);
  }

  // ---- inverse outer: IDFT16 over j, undo butterfly, undo twiddle
  dft16p<1>(v);
  if (hi) {
#pragma unroll
    for (int r = 1; r < 16; ++r) v[r] = cmulsc(v[r], W32c[r], W32s[r]);
  }
#pragma unroll
  for (int r = 0; r < 16; ++r) {
    u64 g = __shfl_xor_sync(0xFFFFFFFFu, v[r], 16);
    v[r] = pfma(v[r], SGN, g);          // low: p + qWbar ; high: p - qWbar
  }
  {
    const float thb = 2.f * PIf * (1.f / 512.f) * (float)(lane & 15);
    if (hi) { float sn, cs; __sincosf(thb * 16.f, &sn, &cs); v[0] = cmulsc(v[0], cs, sn); }
#pragma unroll
    for (int r = 1; r < 16; ++r) {
      float sn, cs; __sincosf(thb * (float)(r + (lane & 16)), &sn, &cs);
      v[r] = cmulsc(v[r], cs, sn);
    }
  }

  // ---- E2 (smem): back to (lane holds all k16)
  {
    const int k16u = lane & 15, off = lane & 16;
#pragma unroll
    for (int r = 0; r < 16; ++r)
      sm[w][((r + off) << 4) | (k16u ^ r)] = v[r];
  }
  __syncwarp();
  {
    const int lb = lane & 15;
#pragma unroll
    for (int k16 = 0; k16 < 16; ++k16)
      v[k16] = sm[w][(lane << 4) | (k16 ^ lb)];
  }

  // ---- inverse inner: IDFT16 over k16 -> m, store (coalesced per m)
  dft16p<1>(v);

  float* __restrict__ o1 = out + off1;
  float* __restrict__ o2 = out + off2;
#pragma unroll
  for (int m = 0; m < 16; ++m) {
    float re, im; unpk(v[m], re, im);
    o1[(m << 5) + lane] = re;   // Re -> batch w
    o2[(m << 5) + lane] = im;   // Im -> batch w+4
  }
}

} // namespace

extern "C" void kernel_launch(void* const* d_in, const int* in_sizes, int n_in,
                              void* d_out, int out_size) {
  const float* x   = (const float*)d_in[0];
  // d_in[1] is the (unused) mask
  const float* wgt = (const float*)d_in[2];
  float* out       = (float*)d_out;
  sgn_fft_kernel<<<Hh * Ll, 128>>>(x, wgt, out);
}